// round 3
// baseline (speedup 1.0000x reference)
#include <cuda_runtime.h>
#include <math.h>

#define BATCH 8
#define HP 256        // pooled H/W
#define HF 512        // full H/W

// Scratch (device globals — no allocation allowed)
__device__ float g_pool[2][BATCH][HP][HP];        // pooled fixed, moved (4MB)
__device__ float g_diff[BATCH * 8][HP][HP];       // mind descriptor diff (16MB)
__device__ unsigned int g_hist_part[BATCH][16][256];
__device__ float g_part_mind[1024];
__device__ float g_part_reg[128];

__device__ __forceinline__ float san(float v) { return (v == v) ? v : 0.0f; }
__device__ __forceinline__ int clampi(int v, int lo, int hi) { return min(max(v, lo), hi); }

// ---- 2x2 avg pool (fixed, moved) + per-strip joint histogram (no atomics to gmem) ----
// grid: p(2) x b(8) x strip(16), 256 threads; each block = 16 pooled rows.
__global__ __launch_bounds__(256) void k_pool(const float* __restrict__ fixed,
                                              const float* __restrict__ moved) {
    int blk = blockIdx.x;
    int st = blk & 15;
    int b = (blk >> 4) & 7;
    int p = blk >> 7;
    const float* src = (p == 0 ? fixed : moved) + (size_t)b * HF * HF;
    const float* msrc = moved + (size_t)b * HF * HF;

    __shared__ unsigned int sh[256];
    if (p == 0) {
        sh[threadIdx.x] = 0u;
        __syncthreads();
    }

    int x = threadIdx.x;
    for (int r = 0; r < 16; r++) {
        int y = st * 16 + r;
        const float2* r0 = (const float2*)(src + (size_t)(2 * y) * HF) + x;
        float2 t0 = r0[0];
        float2 t1 = r0[HF / 2];
        float a = san(t0.x);
        float pooled = 0.25f * (a + san(t0.y) + san(t1.x) + san(t1.y));
        g_pool[p][b][y][x] = pooled;
        if (p == 0) {
            float2 m2 = ((const float2*)(msrc + (size_t)(2 * y) * HF))[x];
            float mv = san(m2.x);
            float xf = fminf(fmaxf((a + 1.0f) * 0.5f, 0.001f), 0.999f);
            float yf = fminf(fmaxf((mv + 1.0f) * 0.5f, 0.001f), 0.999f);
            // searchsorted(linspace(0,1,17), v, 'left') - 1 == ceil(v*16)-1 on exact grid
            int xb = clampi((int)ceilf(xf * 16.0f) - 1, 0, 15);
            int yb = clampi((int)ceilf(yf * 16.0f) - 1, 0, 15);
            atomicAdd(&sh[xb * 16 + yb], 1u);
        }
    }
    if (p == 0) {
        __syncthreads();
        g_hist_part[b][st][threadIdx.x] = sh[threadIdx.x];
    }
}

// ---------------- MIND descriptors for both images, write diff ----------------
#define BX 32
#define BY 16
#define SW 38   // BX + 6
__global__ __launch_bounds__(512) void k_mind() {
    __shared__ float sF[BY + 6][SW];
    __shared__ float sM[BY + 6][SW];
    __shared__ float hF[BY + 4][BX + 2];   // horizontal 3-sums for patch mean
    __shared__ float hM[BY + 4][BX + 2];
    __shared__ float vF[BY + 2][BX + 2];
    __shared__ float vM[BY + 2][BX + 2];
    __shared__ float hvF[BY + 2][BX];      // horizontal 3-sums of variance
    __shared__ float hvM[BY + 2][BX];

    int b = blockIdx.z;
    int tileX = blockIdx.x * BX, tileY = blockIdx.y * BY;
    int gx0 = tileX - 3, gy0 = tileY - 3;
    int tid = threadIdx.y * BX + threadIdx.x;
    int ty = threadIdx.y, tx = threadIdx.x;
    const float* imF = &g_pool[0][b][0][0];
    const float* imM = &g_pool[1][b][0][0];

    bool interior = (blockIdx.x >= 1) && (blockIdx.x <= 6) &&
                    (blockIdx.y >= 1) && (blockIdx.y <= 14);

    const int offdx[8] = {-2, -2, -2, 0, 0, 2, 2, 2};
    const int offdy[8] = {-2, 0, 2, -2, 2, -2, 0, 2};

    float cF, cM, invF, invM;

    if (interior) {
        // ---- fast path: no index clamping anywhere ----
        for (int s = tid; s < (BY + 6) * SW; s += 512) {
            int sy = s / SW, sx = s % SW;
            const float* rowF = imF + (gy0 + sy) * HP + gx0;
            const float* rowM = imM + (gy0 + sy) * HP + gx0;
            sF[sy][sx] = rowF[sx];
            sM[sy][sx] = rowM[sx];
        }
        __syncthreads();

        // horizontal 3-sum (taps vc-2..vc); row r = global row tileY-3+r
        for (int s = tid; s < (BY + 4) * (BX + 2); s += 512) {
            int sy = s / (BX + 2), sx = s % (BX + 2);
            hF[sy][sx] = sF[sy][sx] + sF[sy][sx + 1] + sF[sy][sx + 2];
            hM[sy][sx] = sM[sy][sx] + sM[sy][sx + 1] + sM[sy][sx + 2];
        }
        __syncthreads();

        // variance_pre at (uc,vc) = (tileY-1+sy, tileX-1+sx)
        for (int s = tid; s < (BY + 2) * (BX + 2); s += 512) {
            int sy = s / (BX + 2), sx = s % (BX + 2);
            float pmF = hF[sy][sx] + hF[sy + 1][sx] + hF[sy + 2][sx];
            float pmM = hM[sy][sx] + hM[sy + 1][sx] + hM[sy + 2][sx];
            float dF = sF[sy + 2][sx + 2] - pmF * (1.0f / 9.0f);
            float dM = sM[sy + 2][sx + 2] - pmM * (1.0f / 9.0f);
            vF[sy][sx] = dF * dF;
            vM[sy][sx] = dM * dM;
        }
        __syncthreads();

        // horizontal 3-sum of variance
        for (int s = tid; s < (BY + 2) * BX; s += 512) {
            int sy = s >> 5, sx = s & 31;
            hvF[sy][sx] = vF[sy][sx] + vF[sy][sx + 1] + vF[sy][sx + 2];
            hvM[sy][sx] = vM[sy][sx] + vM[sy][sx + 1] + vM[sy][sx + 2];
        }
        __syncthreads();

        float varF = fmaxf((hvF[ty][tx] + hvF[ty + 1][tx] + hvF[ty + 2][tx]) * (1.0f / 9.0f), 1e-4f);
        float varM = fmaxf((hvM[ty][tx] + hvM[ty + 1][tx] + hvM[ty + 2][tx]) * (1.0f / 9.0f), 1e-4f);
        invF = 1.0f / (varF * 2.0f + 1e-6f);
        invM = 1.0f / (varM * 2.0f + 1e-6f);
        cF = sF[ty + 3][tx + 3];
        cM = sM[ty + 3][tx + 3];
    } else {
        // ---- border path: exact clamped semantics ----
        for (int s = tid; s < (BY + 6) * SW; s += 512) {
            int sy = s / SW, sx = s % SW;
            int gy = clampi(gy0 + sy, 0, HP - 1);
            int gx = clampi(gx0 + sx, 0, HP - 1);
            sF[sy][sx] = imF[gy * HP + gx];
            sM[sy][sx] = imM[gy * HP + gx];
        }
        __syncthreads();

        for (int s = tid; s < (BY + 2) * (BX + 2); s += 512) {
            int sy = s / (BX + 2), sx = s % (BX + 2);
            int uc = clampi(tileY - 1 + sy, 0, HP - 1);
            int vc = clampi(tileX - 1 + sx, 0, HP - 1);
            float pmF = 0.f, pmM = 0.f;
            #pragma unroll
            for (int a = 0; a < 3; a++) {
                int rr = clampi(uc - 2 + a, 0, HP - 1) - gy0;
                #pragma unroll
                for (int bb = 0; bb < 3; bb++) {
                    int cc = clampi(vc - 2 + bb, 0, HP - 1) - gx0;
                    pmF += sF[rr][cc];
                    pmM += sM[rr][cc];
                }
            }
            float dF = sF[uc - gy0][vc - gx0] - pmF * (1.0f / 9.0f);
            float dM = sM[uc - gy0][vc - gx0] - pmM * (1.0f / 9.0f);
            vF[sy][sx] = dF * dF;
            vM[sy][sx] = dM * dM;
        }
        __syncthreads();

        int y = tileY + ty, x = tileX + tx;
        float vsF = 0.f, vsM = 0.f;
        #pragma unroll
        for (int a = -1; a <= 1; a++) {
            int rr = clampi(y + a, 0, HP - 1) - (tileY - 1);
            #pragma unroll
            for (int bb = -1; bb <= 1; bb++) {
                int cc = clampi(x + bb, 0, HP - 1) - (tileX - 1);
                vsF += vF[rr][cc];
                vsM += vM[rr][cc];
            }
        }
        float varF = fmaxf(vsF * (1.0f / 9.0f), 1e-4f);
        float varM = fmaxf(vsM * (1.0f / 9.0f), 1e-4f);
        invF = 1.0f / (varF * 2.0f + 1e-6f);
        invM = 1.0f / (varM * 2.0f + 1e-6f);
        cF = sF[ty + 3][tx + 3];   // (y - gy0, x - gx0)
        cM = sM[ty + 3][tx + 3];
    }

    int y = tileY + ty, x = tileX + tx;
    float eF[8], eM[8];
    float sumF = 0.f, sumM = 0.f;
    if (interior) {
        #pragma unroll
        for (int c = 0; c < 8; c++) {
            float oF = sF[ty + 3 + offdy[c]][tx + 3 + offdx[c]];
            float oM = sM[ty + 3 + offdy[c]][tx + 3 + offdx[c]];
            float dfF = cF - oF, dfM = cM - oM;
            float qF = fminf(dfF * dfF * invF, 50.0f);
            float qM = fminf(dfM * dfM * invM, 50.0f);
            eF[c] = __expf(-qF);
            eM[c] = __expf(-qM);
            sumF += eF[c];
            sumM += eM[c];
        }
    } else {
        #pragma unroll
        for (int c = 0; c < 8; c++) {
            int rr = clampi(y + offdy[c], 0, HP - 1) - gy0;
            int cc = clampi(x + offdx[c], 0, HP - 1) - gx0;
            float oF = sF[rr][cc], oM = sM[rr][cc];
            float dfF = cF - oF, dfM = cM - oM;
            float qF = fminf(dfF * dfF * invF, 50.0f);
            float qM = fminf(dfM * dfM * invM, 50.0f);
            eF[c] = __expf(-qF);
            eM[c] = __expf(-qM);
            sumF += eF[c];
            sumM += eM[c];
        }
    }
    float rF = 1.0f / (sumF + 1e-8f), rM = 1.0f / (sumM + 1e-8f);
    #pragma unroll
    for (int c = 0; c < 8; c++) {
        g_diff[b * 8 + c][y][x] = eF[c] * rF - eM[c] * rM;
    }
}

// ------ bilinear upsample (align corners) of diff, |.| partial sums ------
#define UP_ROWS 32
__global__ __launch_bounds__(512) void k_up() {
    const float SCALE = 255.0f / 511.0f;
    __shared__ float xup[18][512];
    __shared__ float red[512];

    int plane = blockIdx.x >> 4;
    int strip = blockIdx.x & 15;
    int yo0 = strip * UP_ROWS;

    int rlo = clampi((int)floorf((float)yo0 * SCALE), 0, HP - 2);
    int rhi = clampi((int)floorf((float)(yo0 + UP_ROWS - 1) * SCALE), 0, HP - 2) + 1;
    int nrows = rhi - rlo + 1;

    int t = threadIdx.x;
    float px = (float)t * SCALE;
    int j0 = clampi((int)floorf(px), 0, HP - 2);
    float fx = px - (float)j0;
    const float* base = &g_diff[plane][0][0];
    for (int r = 0; r < nrows; r++) {
        const float* row = base + (rlo + r) * HP;
        xup[r][t] = row[j0] * (1.0f - fx) + row[j0 + 1] * fx;
    }
    __syncthreads();

    float acc = 0.f;
    #pragma unroll
    for (int l = 0; l < UP_ROWS; l++) {
        float pos = (float)(yo0 + l) * SCALE;
        int i0 = clampi((int)floorf(pos), 0, HP - 2);
        float fy = pos - (float)i0;
        float v0 = xup[i0 - rlo][t];
        float v1 = xup[i0 - rlo + 1][t];
        acc += fabsf(v0 * (1.0f - fy) + v1 * fy);
    }
    red[t] = acc;
    __syncthreads();
    #pragma unroll
    for (int s = 256; s > 0; s >>= 1) {
        if (t < s) red[t] += red[t + s];
        __syncthreads();
    }
    if (t == 0) g_part_mind[blockIdx.x] = red[0];
}

// ---- regularizer: fused 2x2 pool of flow + sobel/laplacian stencils + reduce ----
// grid: b(8) x strip(16), 256 threads; 16 output rows per block, 18 pooled rows in smem.
__global__ __launch_bounds__(256) void k_reg(const float* __restrict__ flow) {
    __shared__ float su[18][256];
    __shared__ float sv[18][256];
    int b = blockIdx.x >> 4;
    int st = blockIdx.x & 15;
    const float* uf = flow + (size_t)b * 2 * HF * HF;
    const float* vf = uf + (size_t)HF * HF;
    int x = threadIdx.x;

    for (int r = 0; r < 18; r++) {
        int py = clampi(st * 16 - 1 + r, 0, HP - 1);
        const float2* u0 = (const float2*)(uf + (size_t)(2 * py) * HF) + x;
        float2 ua = u0[0], ub = u0[HF / 2];
        su[r][x] = 0.25f * (san(ua.x) + san(ua.y) + san(ub.x) + san(ub.y));
        const float2* v0 = (const float2*)(vf + (size_t)(2 * py) * HF) + x;
        float2 va = v0[0], vb = v0[HF / 2];
        sv[r][x] = 0.25f * (san(va.x) + san(va.y) + san(vb.x) + san(vb.y));
    }
    __syncthreads();

    int xm = max(x - 1, 0), xp = min(x + 1, HP - 1);
    float acc = 0.f;
    #pragma unroll 4
    for (int j = 0; j < 16; j++) {
        int r = j + 1;
        float u00 = su[r - 1][xm], u01 = su[r - 1][x], u02 = su[r - 1][xp];
        float u10 = su[r][xm],     u11 = su[r][x],     u12 = su[r][xp];
        float u20 = su[r + 1][xm], u21 = su[r + 1][x], u22 = su[r + 1][xp];
        float v00 = sv[r - 1][xm], v01 = sv[r - 1][x], v02 = sv[r - 1][xp];
        float v10 = sv[r][xm],     v11 = sv[r][x],     v12 = sv[r][xp];
        float v20 = sv[r + 1][xm], v21 = sv[r + 1][x], v22 = sv[r + 1][xp];

        float gxu = (u02 + 2.f * u12 + u22) - (u00 + 2.f * u10 + u20);
        float gyu = (u20 + 2.f * u21 + u22) - (u00 + 2.f * u01 + u02);
        float lpu = u01 + u10 + u12 + u21 - 4.f * u11;
        float gxv = (v02 + 2.f * v12 + v22) - (v00 + 2.f * v10 + v20);
        float gyv = (v20 + 2.f * v21 + v22) - (v00 + 2.f * v01 + v02);
        float lpv = v01 + v10 + v12 + v21 - 4.f * v11;

        float gm = gxu * gxu + gyu * gyu + gxv * gxv + gyv * gyv;
        float lm = lpu * lpu + lpv * lpv;
        acc += fminf(gm, 100.0f) + fminf(lm, 100.0f);
    }

    __shared__ float red[256];
    red[x] = acc;
    __syncthreads();
    #pragma unroll
    for (int s = 128; s > 0; s >>= 1) {
        if (x < s) red[x] += red[x + s];
        __syncthreads();
    }
    if (x == 0) g_part_reg[blockIdx.x] = red[0];
}

// -------- fused epilogue: reduce mind + reg partials, MI/NMI, combine --------
__global__ __launch_bounds__(1024) void k_final(float* __restrict__ out) {
    int t = threadIdx.x;
    __shared__ float red[1024];
    __shared__ float s_mind, s_reg, s_nmi;
    __shared__ float hp[256];
    __shared__ float xh[16], yh[16];

    // mind partials (1024)
    red[t] = g_part_mind[t];
    __syncthreads();
    #pragma unroll
    for (int s = 512; s > 0; s >>= 1) {
        if (t < s) red[t] += red[t + s];
        __syncthreads();
    }
    if (t == 0) s_mind = red[0];
    __syncthreads();

    // reg partials (128)
    red[t] = (t < 128) ? g_part_reg[t] : 0.0f;
    __syncthreads();
    #pragma unroll
    for (int s = 512; s > 0; s >>= 1) {
        if (t < s) red[t] += red[t + s];
        __syncthreads();
    }
    if (t == 0) { s_reg = red[0]; s_nmi = 0.f; }
    __syncthreads();

    // MI / NMI per batch
    for (int b = 0; b < BATCH; b++) {
        float p = 0.f;
        if (t < 256) {
            unsigned int cnt = 0;
            #pragma unroll
            for (int st = 0; st < 16; st++) cnt += g_hist_part[b][st][t];
            p = (float)cnt * (1.0f / 65536.0f);
            hp[t] = p;
        }
        __syncthreads();
        if (t < 16) {
            float s = 0.f;
            for (int j = 0; j < 16; j++) s += hp[t * 16 + j];
            xh[t] = s + 1e-5f;
            float s2 = 0.f;
            for (int i2 = 0; i2 < 16; i2++) s2 += hp[i2 * 16 + t];
            yh[t] = s2 + 1e-5f;
        }
        __syncthreads();
        if (t < 256) {
            float hpe = p + 1e-5f;
            red[t] = hpe * (logf(hpe) - logf(xh[t >> 4] * yh[t & 15]));
        }
        __syncthreads();
        #pragma unroll
        for (int s = 128; s > 0; s >>= 1) {
            if (t < s) red[t] += red[t + s];
            __syncthreads();
        }
        if (t == 0) {
            float mi = red[0];
            float hx = 0.f, hy = 0.f;
            for (int k = 0; k < 16; k++) {
                hx -= xh[k] * logf(xh[k]);
                hy -= yh[k] * logf(yh[k]);
            }
            float se = hx + hy;
            float nmi = (se < 1e-10f) ? 0.0f : 2.0f * mi / se;
            s_nmi += fminf(fmaxf(nmi, -1.0f), 1.0f);
        }
        __syncthreads();
    }

    if (t == 0) {
        float m = s_nmi * (1.0f / BATCH);
        m = fminf(fmaxf(m, -1.0f), 1.0f);
        out[0] = -m
               + 5.0f * (s_mind * (1.0f / 16777216.0f))
               + 0.1f * (s_reg * (1.0f / 524288.0f));
    }
}

// ---------------- launch ----------------
extern "C" void kernel_launch(void* const* d_in, const int* in_sizes, int n_in,
                              void* d_out, int out_size) {
    const float* fixed = (const float*)d_in[0];
    const float* moved = (const float*)d_in[1];
    const float* flow  = (const float*)d_in[2];
    if (n_in >= 3) {
        int fi = -1;
        for (int i = 0; i < 3; i++) if (in_sizes[i] == 2 * BATCH * HF * HF) fi = i;
        if (fi == 0) { flow = (const float*)d_in[0]; fixed = (const float*)d_in[1]; moved = (const float*)d_in[2]; }
        else if (fi == 1) { fixed = (const float*)d_in[0]; flow = (const float*)d_in[1]; moved = (const float*)d_in[2]; }
    }

    k_pool<<<256, 256>>>(fixed, moved);
    k_mind<<<dim3(HP / BX, HP / BY, BATCH), dim3(BX, BY)>>>();
    k_up<<<1024, 512>>>();
    k_reg<<<128, 256>>>(flow);
    k_final<<<1, 1024>>>((float*)d_out);
}

// round 4
// speedup vs baseline: 1.0251x; 1.0251x over previous
#include <cuda_runtime.h>
#include <cuda_fp16.h>
#include <math.h>

#define BATCH 8
#define HP 256        // pooled H/W
#define HF 512        // full H/W

// Scratch (device globals — no allocation allowed)
__device__ float g_pool[2][BATCH][HP][HP];        // pooled fixed, moved (4MB)
__device__ __half g_diff[BATCH * 8][HP][HP];      // mind descriptor diff (8MB, fp16)
__device__ unsigned int g_hist_part[BATCH][32][256];
__device__ float g_part_mind[1024];
__device__ float g_part_reg[512];

__device__ __forceinline__ float san(float v) { return (v == v) ? v : 0.0f; }
__device__ __forceinline__ int clampi(int v, int lo, int hi) { return min(max(v, lo), hi); }

// ============ fused front-end: pool fixed (+hist), pool moved, flow regularizer ====
// grid 1024 x 256 threads:
//   blocks [0,256):    pool fixed, strip of 8 rows, + joint histogram partials
//   blocks [256,512):  pool moved
//   blocks [512,1024): regularizer, strip of 4 pooled rows
__global__ __launch_bounds__(256) void k_front(const float* __restrict__ fixed,
                                               const float* __restrict__ moved,
                                               const float* __restrict__ flow) {
    int blk = blockIdx.x;
    int t = threadIdx.x;

    if (blk < 512) {
        int p = blk >> 8;            // 0 fixed, 1 moved
        int b = (blk >> 5) & 7;
        int st = blk & 31;           // 8 pooled rows per strip
        const float* src = (p == 0 ? fixed : moved) + (size_t)b * HF * HF;
        const float* msrc = moved + (size_t)b * HF * HF;

        __shared__ unsigned int sh[256];
        if (p == 0) {
            sh[t] = 0u;
            __syncthreads();
        }

        #pragma unroll 2
        for (int r = 0; r < 8; r++) {
            int y = st * 8 + r;
            const float2* r0 = (const float2*)(src + (size_t)(2 * y) * HF) + t;
            float2 t0 = r0[0];
            float2 t1 = r0[HF / 2];
            float a = san(t0.x);
            g_pool[p][b][y][t] = 0.25f * (a + san(t0.y) + san(t1.x) + san(t1.y));
            if (p == 0) {
                float2 m2 = ((const float2*)(msrc + (size_t)(2 * y) * HF))[t];
                float mv = san(m2.x);
                float xf = fminf(fmaxf((a + 1.0f) * 0.5f, 0.001f), 0.999f);
                float yf = fminf(fmaxf((mv + 1.0f) * 0.5f, 0.001f), 0.999f);
                // searchsorted(linspace(0,1,17),v,'left')-1 == ceil(v*16)-1 on exact grid
                int xb = clampi((int)ceilf(xf * 16.0f) - 1, 0, 15);
                int yb = clampi((int)ceilf(yf * 16.0f) - 1, 0, 15);
                atomicAdd(&sh[xb * 16 + yb], 1u);
            }
        }
        if (p == 0) {
            __syncthreads();
            g_hist_part[b][st][t] = sh[t];
        }
    } else {
        // ---- regularizer: fused pool of flow + sobel/laplacian, 4 rows per block ----
        int q = blk - 512;
        int b = q >> 6;
        int st = q & 63;
        const float* uf = flow + (size_t)b * 2 * HF * HF;
        const float* vf = uf + (size_t)HF * HF;

        __shared__ float su[6][256];
        __shared__ float sv[6][256];

        #pragma unroll
        for (int r = 0; r < 6; r++) {
            int py = clampi(st * 4 - 1 + r, 0, HP - 1);
            const float2* u0 = (const float2*)(uf + (size_t)(2 * py) * HF) + t;
            float2 ua = u0[0], ub = u0[HF / 2];
            su[r][t] = 0.25f * (san(ua.x) + san(ua.y) + san(ub.x) + san(ub.y));
            const float2* v0 = (const float2*)(vf + (size_t)(2 * py) * HF) + t;
            float2 va = v0[0], vb = v0[HF / 2];
            sv[r][t] = 0.25f * (san(va.x) + san(va.y) + san(vb.x) + san(vb.y));
        }
        __syncthreads();

        int xm = max(t - 1, 0), xp = min(t + 1, HP - 1);
        float acc = 0.f;
        #pragma unroll
        for (int j = 0; j < 4; j++) {
            int r = j + 1;
            float u00 = su[r - 1][xm], u01 = su[r - 1][t], u02 = su[r - 1][xp];
            float u10 = su[r][xm],     u11 = su[r][t],     u12 = su[r][xp];
            float u20 = su[r + 1][xm], u21 = su[r + 1][t], u22 = su[r + 1][xp];
            float v00 = sv[r - 1][xm], v01 = sv[r - 1][t], v02 = sv[r - 1][xp];
            float v10 = sv[r][xm],     v11 = sv[r][t],     v12 = sv[r][xp];
            float v20 = sv[r + 1][xm], v21 = sv[r + 1][t], v22 = sv[r + 1][xp];

            float gxu = (u02 + 2.f * u12 + u22) - (u00 + 2.f * u10 + u20);
            float gyu = (u20 + 2.f * u21 + u22) - (u00 + 2.f * u01 + u02);
            float lpu = u01 + u10 + u12 + u21 - 4.f * u11;
            float gxv = (v02 + 2.f * v12 + v22) - (v00 + 2.f * v10 + v20);
            float gyv = (v20 + 2.f * v21 + v22) - (v00 + 2.f * v01 + v02);
            float lpv = v01 + v10 + v12 + v21 - 4.f * v11;

            float gm = gxu * gxu + gyu * gyu + gxv * gxv + gyv * gyv;
            float lm = lpu * lpu + lpv * lpv;
            acc += fminf(gm, 100.0f) + fminf(lm, 100.0f);
        }

        __shared__ float red[256];
        red[t] = acc;
        __syncthreads();
        #pragma unroll
        for (int s = 128; s > 0; s >>= 1) {
            if (t < s) red[t] += red[t + s];
            __syncthreads();
        }
        if (t == 0) g_part_reg[q] = red[0];
    }
}

// ---------------- MIND descriptors for both images, write diff (fp16) ----------------
#define BX 32
#define BY 16
#define SW 38   // BX + 6
__global__ __launch_bounds__(512) void k_mind() {
    __shared__ float sF[BY + 6][SW];
    __shared__ float sM[BY + 6][SW];
    __shared__ float hF[BY + 4][BX + 2];
    __shared__ float hM[BY + 4][BX + 2];
    __shared__ float vF[BY + 2][BX + 2];
    __shared__ float vM[BY + 2][BX + 2];
    __shared__ float hvF[BY + 2][BX];
    __shared__ float hvM[BY + 2][BX];

    int b = blockIdx.z;
    int tileX = blockIdx.x * BX, tileY = blockIdx.y * BY;
    int gx0 = tileX - 3, gy0 = tileY - 3;
    int tid = threadIdx.y * BX + threadIdx.x;
    int ty = threadIdx.y, tx = threadIdx.x;
    const float* imF = &g_pool[0][b][0][0];
    const float* imM = &g_pool[1][b][0][0];

    bool interior = (blockIdx.x >= 1) && (blockIdx.x <= 6) &&
                    (blockIdx.y >= 1) && (blockIdx.y <= 14);

    const int offdx[8] = {-2, -2, -2, 0, 0, 2, 2, 2};
    const int offdy[8] = {-2, 0, 2, -2, 2, -2, 0, 2};

    float cF, cM, invF, invM;

    if (interior) {
        for (int s = tid; s < (BY + 6) * SW; s += 512) {
            int sy = s / SW, sx = s % SW;
            sF[sy][sx] = imF[(gy0 + sy) * HP + gx0 + sx];
            sM[sy][sx] = imM[(gy0 + sy) * HP + gx0 + sx];
        }
        __syncthreads();

        for (int s = tid; s < (BY + 4) * (BX + 2); s += 512) {
            int sy = s / (BX + 2), sx = s % (BX + 2);
            hF[sy][sx] = sF[sy][sx] + sF[sy][sx + 1] + sF[sy][sx + 2];
            hM[sy][sx] = sM[sy][sx] + sM[sy][sx + 1] + sM[sy][sx + 2];
        }
        __syncthreads();

        for (int s = tid; s < (BY + 2) * (BX + 2); s += 512) {
            int sy = s / (BX + 2), sx = s % (BX + 2);
            float pmF = hF[sy][sx] + hF[sy + 1][sx] + hF[sy + 2][sx];
            float pmM = hM[sy][sx] + hM[sy + 1][sx] + hM[sy + 2][sx];
            float dF = sF[sy + 2][sx + 2] - pmF * (1.0f / 9.0f);
            float dM = sM[sy + 2][sx + 2] - pmM * (1.0f / 9.0f);
            vF[sy][sx] = dF * dF;
            vM[sy][sx] = dM * dM;
        }
        __syncthreads();

        for (int s = tid; s < (BY + 2) * BX; s += 512) {
            int sy = s >> 5, sx = s & 31;
            hvF[sy][sx] = vF[sy][sx] + vF[sy][sx + 1] + vF[sy][sx + 2];
            hvM[sy][sx] = vM[sy][sx] + vM[sy][sx + 1] + vM[sy][sx + 2];
        }
        __syncthreads();

        float varF = fmaxf((hvF[ty][tx] + hvF[ty + 1][tx] + hvF[ty + 2][tx]) * (1.0f / 9.0f), 1e-4f);
        float varM = fmaxf((hvM[ty][tx] + hvM[ty + 1][tx] + hvM[ty + 2][tx]) * (1.0f / 9.0f), 1e-4f);
        invF = 1.0f / (varF * 2.0f + 1e-6f);
        invM = 1.0f / (varM * 2.0f + 1e-6f);
        cF = sF[ty + 3][tx + 3];
        cM = sM[ty + 3][tx + 3];
    } else {
        for (int s = tid; s < (BY + 6) * SW; s += 512) {
            int sy = s / SW, sx = s % SW;
            int gy = clampi(gy0 + sy, 0, HP - 1);
            int gx = clampi(gx0 + sx, 0, HP - 1);
            sF[sy][sx] = imF[gy * HP + gx];
            sM[sy][sx] = imM[gy * HP + gx];
        }
        __syncthreads();

        for (int s = tid; s < (BY + 2) * (BX + 2); s += 512) {
            int sy = s / (BX + 2), sx = s % (BX + 2);
            int uc = clampi(tileY - 1 + sy, 0, HP - 1);
            int vc = clampi(tileX - 1 + sx, 0, HP - 1);
            float pmF = 0.f, pmM = 0.f;
            #pragma unroll
            for (int a = 0; a < 3; a++) {
                int rr = clampi(uc - 2 + a, 0, HP - 1) - gy0;
                #pragma unroll
                for (int bb = 0; bb < 3; bb++) {
                    int cc = clampi(vc - 2 + bb, 0, HP - 1) - gx0;
                    pmF += sF[rr][cc];
                    pmM += sM[rr][cc];
                }
            }
            float dF = sF[uc - gy0][vc - gx0] - pmF * (1.0f / 9.0f);
            float dM = sM[uc - gy0][vc - gx0] - pmM * (1.0f / 9.0f);
            vF[sy][sx] = dF * dF;
            vM[sy][sx] = dM * dM;
        }
        __syncthreads();

        int y = tileY + ty, x = tileX + tx;
        float vsF = 0.f, vsM = 0.f;
        #pragma unroll
        for (int a = -1; a <= 1; a++) {
            int rr = clampi(y + a, 0, HP - 1) - (tileY - 1);
            #pragma unroll
            for (int bb = -1; bb <= 1; bb++) {
                int cc = clampi(x + bb, 0, HP - 1) - (tileX - 1);
                vsF += vF[rr][cc];
                vsM += vM[rr][cc];
            }
        }
        float varF = fmaxf(vsF * (1.0f / 9.0f), 1e-4f);
        float varM = fmaxf(vsM * (1.0f / 9.0f), 1e-4f);
        invF = 1.0f / (varF * 2.0f + 1e-6f);
        invM = 1.0f / (varM * 2.0f + 1e-6f);
        cF = sF[ty + 3][tx + 3];
        cM = sM[ty + 3][tx + 3];
    }

    int y = tileY + ty, x = tileX + tx;
    float eF[8], eM[8];
    float sumF = 0.f, sumM = 0.f;
    if (interior) {
        #pragma unroll
        for (int c = 0; c < 8; c++) {
            float oF = sF[ty + 3 + offdy[c]][tx + 3 + offdx[c]];
            float oM = sM[ty + 3 + offdy[c]][tx + 3 + offdx[c]];
            float dfF = cF - oF, dfM = cM - oM;
            float qF = fminf(dfF * dfF * invF, 50.0f);
            float qM = fminf(dfM * dfM * invM, 50.0f);
            eF[c] = __expf(-qF);
            eM[c] = __expf(-qM);
            sumF += eF[c];
            sumM += eM[c];
        }
    } else {
        #pragma unroll
        for (int c = 0; c < 8; c++) {
            int rr = clampi(y + offdy[c], 0, HP - 1) - gy0;
            int cc = clampi(x + offdx[c], 0, HP - 1) - gx0;
            float oF = sF[rr][cc], oM = sM[rr][cc];
            float dfF = cF - oF, dfM = cM - oM;
            float qF = fminf(dfF * dfF * invF, 50.0f);
            float qM = fminf(dfM * dfM * invM, 50.0f);
            eF[c] = __expf(-qF);
            eM[c] = __expf(-qM);
            sumF += eF[c];
            sumM += eM[c];
        }
    }
    float rF = 1.0f / (sumF + 1e-8f), rM = 1.0f / (sumM + 1e-8f);
    #pragma unroll
    for (int c = 0; c < 8; c++) {
        g_diff[b * 8 + c][y][x] = __float2half(eF[c] * rF - eM[c] * rM);
    }
}

// ------ bilinear upsample (align corners) of diff, |.| partial sums ------
#define UP_ROWS 32
__global__ __launch_bounds__(512) void k_up() {
    const float SCALE = 255.0f / 511.0f;
    __shared__ float xup[18][512];
    __shared__ float red[512];

    int plane = blockIdx.x >> 4;
    int strip = blockIdx.x & 15;
    int yo0 = strip * UP_ROWS;

    int rlo = clampi((int)floorf((float)yo0 * SCALE), 0, HP - 2);
    int rhi = clampi((int)floorf((float)(yo0 + UP_ROWS - 1) * SCALE), 0, HP - 2) + 1;
    int nrows = rhi - rlo + 1;

    int t = threadIdx.x;
    float px = (float)t * SCALE;
    int j0 = clampi((int)floorf(px), 0, HP - 2);
    float fx = px - (float)j0;
    const __half* base = &g_diff[plane][0][0];
    for (int r = 0; r < nrows; r++) {
        const __half* row = base + (rlo + r) * HP;
        xup[r][t] = __half2float(row[j0]) * (1.0f - fx) + __half2float(row[j0 + 1]) * fx;
    }
    __syncthreads();

    float acc = 0.f;
    #pragma unroll
    for (int l = 0; l < UP_ROWS; l++) {
        float pos = (float)(yo0 + l) * SCALE;
        int i0 = clampi((int)floorf(pos), 0, HP - 2);
        float fy = pos - (float)i0;
        float v0 = xup[i0 - rlo][t];
        float v1 = xup[i0 - rlo + 1][t];
        acc += fabsf(v0 * (1.0f - fy) + v1 * fy);
    }
    red[t] = acc;
    __syncthreads();
    #pragma unroll
    for (int s = 256; s > 0; s >>= 1) {
        if (t < s) red[t] += red[t + s];
        __syncthreads();
    }
    if (t == 0) g_part_mind[blockIdx.x] = red[0];
}

// -------- fused epilogue: reduce mind + reg partials, MI/NMI, combine --------
__global__ __launch_bounds__(1024) void k_final(float* __restrict__ out) {
    int t = threadIdx.x;
    __shared__ float red[1024];
    __shared__ float s_mind, s_reg, s_nmi;
    __shared__ float hp[256];
    __shared__ float xh[16], yh[16];

    red[t] = g_part_mind[t];
    __syncthreads();
    #pragma unroll
    for (int s = 512; s > 0; s >>= 1) {
        if (t < s) red[t] += red[t + s];
        __syncthreads();
    }
    if (t == 0) s_mind = red[0];
    __syncthreads();

    red[t] = (t < 512) ? g_part_reg[t] : 0.0f;
    __syncthreads();
    #pragma unroll
    for (int s = 512; s > 0; s >>= 1) {
        if (t < s) red[t] += red[t + s];
        __syncthreads();
    }
    if (t == 0) { s_reg = red[0]; s_nmi = 0.f; }
    __syncthreads();

    for (int b = 0; b < BATCH; b++) {
        float p = 0.f;
        if (t < 256) {
            unsigned int cnt = 0;
            #pragma unroll
            for (int st = 0; st < 32; st++) cnt += g_hist_part[b][st][t];
            p = (float)cnt * (1.0f / 65536.0f);
            hp[t] = p;
        }
        __syncthreads();
        if (t < 16) {
            float s = 0.f;
            for (int j = 0; j < 16; j++) s += hp[t * 16 + j];
            xh[t] = s + 1e-5f;
            float s2 = 0.f;
            for (int i2 = 0; i2 < 16; i2++) s2 += hp[i2 * 16 + t];
            yh[t] = s2 + 1e-5f;
        }
        __syncthreads();
        if (t < 256) {
            float hpe = p + 1e-5f;
            red[t] = hpe * (logf(hpe) - logf(xh[t >> 4] * yh[t & 15]));
        }
        __syncthreads();
        #pragma unroll
        for (int s = 128; s > 0; s >>= 1) {
            if (t < s) red[t] += red[t + s];
            __syncthreads();
        }
        if (t == 0) {
            float mi = red[0];
            float hx = 0.f, hy = 0.f;
            for (int k = 0; k < 16; k++) {
                hx -= xh[k] * logf(xh[k]);
                hy -= yh[k] * logf(yh[k]);
            }
            float se = hx + hy;
            float nmi = (se < 1e-10f) ? 0.0f : 2.0f * mi / se;
            s_nmi += fminf(fmaxf(nmi, -1.0f), 1.0f);
        }
        __syncthreads();
    }

    if (t == 0) {
        float m = s_nmi * (1.0f / BATCH);
        m = fminf(fmaxf(m, -1.0f), 1.0f);
        out[0] = -m
               + 5.0f * (s_mind * (1.0f / 16777216.0f))
               + 0.1f * (s_reg * (1.0f / 524288.0f));
    }
}

// ---------------- launch ----------------
extern "C" void kernel_launch(void* const* d_in, const int* in_sizes, int n_in,
                              void* d_out, int out_size) {
    const float* fixed = (const float*)d_in[0];
    const float* moved = (const float*)d_in[1];
    const float* flow  = (const float*)d_in[2];
    if (n_in >= 3) {
        int fi = -1;
        for (int i = 0; i < 3; i++) if (in_sizes[i] == 2 * BATCH * HF * HF) fi = i;
        if (fi == 0) { flow = (const float*)d_in[0]; fixed = (const float*)d_in[1]; moved = (const float*)d_in[2]; }
        else if (fi == 1) { fixed = (const float*)d_in[0]; flow = (const float*)d_in[1]; moved = (const float*)d_in[2]; }
    }

    k_front<<<1024, 256>>>(fixed, moved, flow);
    k_mind<<<dim3(HP / BX, HP / BY, BATCH), dim3(BX, BY)>>>();
    k_up<<<1024, 512>>>();
    k_final<<<1, 1024>>>((float*)d_out);
}

// round 5
// speedup vs baseline: 1.4717x; 1.4356x over previous
#include <cuda_runtime.h>
#include <cuda_fp16.h>
#include <math.h>

#define BATCH 8
#define HP 256        // pooled H/W
#define HF 512        // full H/W

// Scratch (device globals — no allocation allowed)
__device__ float g_pool[2][BATCH][HP][HP];        // pooled fixed, moved (4MB)
__device__ __half g_diff[BATCH * 8][HP][HP];      // mind descriptor diff (8MB, fp16)
__device__ unsigned int g_hist_part[BATCH][32][256];
__device__ float g_part_mind[1024];
__device__ float g_part_reg[512];

__device__ __forceinline__ float san(float v) { return (v == v) ? v : 0.0f; }
__device__ __forceinline__ int clampi(int v, int lo, int hi) { return min(max(v, lo), hi); }

// ============ fused front-end: pool fixed (+hist), pool moved, flow regularizer ====
__global__ __launch_bounds__(256) void k_front(const float* __restrict__ fixed,
                                               const float* __restrict__ moved,
                                               const float* __restrict__ flow) {
    int blk = blockIdx.x;
    int t = threadIdx.x;

    if (blk < 512) {
        int p = blk >> 8;            // 0 fixed, 1 moved
        int b = (blk >> 5) & 7;
        int st = blk & 31;           // 8 pooled rows per strip
        const float* src = (p == 0 ? fixed : moved) + (size_t)b * HF * HF;
        const float* msrc = moved + (size_t)b * HF * HF;

        __shared__ unsigned int sh[256];
        if (p == 0) {
            sh[t] = 0u;
            __syncthreads();
        }

        #pragma unroll 2
        for (int r = 0; r < 8; r++) {
            int y = st * 8 + r;
            const float2* r0 = (const float2*)(src + (size_t)(2 * y) * HF) + t;
            float2 t0 = r0[0];
            float2 t1 = r0[HF / 2];
            float a = san(t0.x);
            g_pool[p][b][y][t] = 0.25f * (a + san(t0.y) + san(t1.x) + san(t1.y));
            if (p == 0) {
                float2 m2 = ((const float2*)(msrc + (size_t)(2 * y) * HF))[t];
                float mv = san(m2.x);
                float xf = fminf(fmaxf((a + 1.0f) * 0.5f, 0.001f), 0.999f);
                float yf = fminf(fmaxf((mv + 1.0f) * 0.5f, 0.001f), 0.999f);
                // searchsorted(linspace(0,1,17),v,'left')-1 == ceil(v*16)-1 on exact grid
                int xb = clampi((int)ceilf(xf * 16.0f) - 1, 0, 15);
                int yb = clampi((int)ceilf(yf * 16.0f) - 1, 0, 15);
                atomicAdd(&sh[xb * 16 + yb], 1u);
            }
        }
        if (p == 0) {
            __syncthreads();
            g_hist_part[b][st][t] = sh[t];
        }
    } else {
        // ---- regularizer: fused pool of flow + sobel/laplacian, 4 rows per block ----
        int q = blk - 512;
        int b = q >> 6;
        int st = q & 63;
        const float* uf = flow + (size_t)b * 2 * HF * HF;
        const float* vf = uf + (size_t)HF * HF;

        __shared__ float su[6][256];
        __shared__ float sv[6][256];

        #pragma unroll
        for (int r = 0; r < 6; r++) {
            int py = clampi(st * 4 - 1 + r, 0, HP - 1);
            const float2* u0 = (const float2*)(uf + (size_t)(2 * py) * HF) + t;
            float2 ua = u0[0], ub = u0[HF / 2];
            su[r][t] = 0.25f * (san(ua.x) + san(ua.y) + san(ub.x) + san(ub.y));
            const float2* v0 = (const float2*)(vf + (size_t)(2 * py) * HF) + t;
            float2 va = v0[0], vb = v0[HF / 2];
            sv[r][t] = 0.25f * (san(va.x) + san(va.y) + san(vb.x) + san(vb.y));
        }
        __syncthreads();

        int xm = max(t - 1, 0), xp = min(t + 1, HP - 1);
        float acc = 0.f;
        #pragma unroll
        for (int j = 0; j < 4; j++) {
            int r = j + 1;
            float u00 = su[r - 1][xm], u01 = su[r - 1][t], u02 = su[r - 1][xp];
            float u10 = su[r][xm],     u11 = su[r][t],     u12 = su[r][xp];
            float u20 = su[r + 1][xm], u21 = su[r + 1][t], u22 = su[r + 1][xp];
            float v00 = sv[r - 1][xm], v01 = sv[r - 1][t], v02 = sv[r - 1][xp];
            float v10 = sv[r][xm],     v11 = sv[r][t],     v12 = sv[r][xp];
            float v20 = sv[r + 1][xm], v21 = sv[r + 1][t], v22 = sv[r + 1][xp];

            float gxu = (u02 + 2.f * u12 + u22) - (u00 + 2.f * u10 + u20);
            float gyu = (u20 + 2.f * u21 + u22) - (u00 + 2.f * u01 + u02);
            float lpu = u01 + u10 + u12 + u21 - 4.f * u11;
            float gxv = (v02 + 2.f * v12 + v22) - (v00 + 2.f * v10 + v20);
            float gyv = (v20 + 2.f * v21 + v22) - (v00 + 2.f * v01 + v02);
            float lpv = v01 + v10 + v12 + v21 - 4.f * v11;

            float gm = gxu * gxu + gyu * gyu + gxv * gxv + gyv * gyv;
            float lm = lpu * lpu + lpv * lpv;
            acc += fminf(gm, 100.0f) + fminf(lm, 100.0f);
        }

        __shared__ float red[256];
        red[t] = acc;
        __syncthreads();
        #pragma unroll
        for (int s = 128; s > 0; s >>= 1) {
            if (t < s) red[t] += red[t + s];
            __syncthreads();
        }
        if (t == 0) g_part_reg[q] = red[0];
    }
}

// ---------------- MIND descriptors for both images, write diff (fp16) ----------------
#define BX 32
#define BY 16
#define SW 38   // BX + 6
__global__ __launch_bounds__(512) void k_mind() {
    __shared__ float sF[BY + 6][SW];
    __shared__ float sM[BY + 6][SW];
    __shared__ float hF[BY + 4][BX + 2];
    __shared__ float hM[BY + 4][BX + 2];
    __shared__ float vF[BY + 2][BX + 2];
    __shared__ float vM[BY + 2][BX + 2];
    __shared__ float hvF[BY + 2][BX];
    __shared__ float hvM[BY + 2][BX];

    int b = blockIdx.z;
    int tileX = blockIdx.x * BX, tileY = blockIdx.y * BY;
    int gx0 = tileX - 3, gy0 = tileY - 3;
    int tid = threadIdx.y * BX + threadIdx.x;
    int ty = threadIdx.y, tx = threadIdx.x;
    const float* imF = &g_pool[0][b][0][0];
    const float* imM = &g_pool[1][b][0][0];

    bool interior = (blockIdx.x >= 1) && (blockIdx.x <= 6) &&
                    (blockIdx.y >= 1) && (blockIdx.y <= 14);

    const int offdx[8] = {-2, -2, -2, 0, 0, 2, 2, 2};
    const int offdy[8] = {-2, 0, 2, -2, 2, -2, 0, 2};

    float cF, cM, invF, invM;

    if (interior) {
        for (int s = tid; s < (BY + 6) * SW; s += 512) {
            int sy = s / SW, sx = s % SW;
            sF[sy][sx] = imF[(gy0 + sy) * HP + gx0 + sx];
            sM[sy][sx] = imM[(gy0 + sy) * HP + gx0 + sx];
        }
        __syncthreads();

        for (int s = tid; s < (BY + 4) * (BX + 2); s += 512) {
            int sy = s / (BX + 2), sx = s % (BX + 2);
            hF[sy][sx] = sF[sy][sx] + sF[sy][sx + 1] + sF[sy][sx + 2];
            hM[sy][sx] = sM[sy][sx] + sM[sy][sx + 1] + sM[sy][sx + 2];
        }
        __syncthreads();

        for (int s = tid; s < (BY + 2) * (BX + 2); s += 512) {
            int sy = s / (BX + 2), sx = s % (BX + 2);
            float pmF = hF[sy][sx] + hF[sy + 1][sx] + hF[sy + 2][sx];
            float pmM = hM[sy][sx] + hM[sy + 1][sx] + hM[sy + 2][sx];
            float dF = sF[sy + 2][sx + 2] - pmF * (1.0f / 9.0f);
            float dM = sM[sy + 2][sx + 2] - pmM * (1.0f / 9.0f);
            vF[sy][sx] = dF * dF;
            vM[sy][sx] = dM * dM;
        }
        __syncthreads();

        for (int s = tid; s < (BY + 2) * BX; s += 512) {
            int sy = s >> 5, sx = s & 31;
            hvF[sy][sx] = vF[sy][sx] + vF[sy][sx + 1] + vF[sy][sx + 2];
            hvM[sy][sx] = vM[sy][sx] + vM[sy][sx + 1] + vM[sy][sx + 2];
        }
        __syncthreads();

        float varF = fmaxf((hvF[ty][tx] + hvF[ty + 1][tx] + hvF[ty + 2][tx]) * (1.0f / 9.0f), 1e-4f);
        float varM = fmaxf((hvM[ty][tx] + hvM[ty + 1][tx] + hvM[ty + 2][tx]) * (1.0f / 9.0f), 1e-4f);
        invF = 1.0f / (varF * 2.0f + 1e-6f);
        invM = 1.0f / (varM * 2.0f + 1e-6f);
        cF = sF[ty + 3][tx + 3];
        cM = sM[ty + 3][tx + 3];
    } else {
        for (int s = tid; s < (BY + 6) * SW; s += 512) {
            int sy = s / SW, sx = s % SW;
            int gy = clampi(gy0 + sy, 0, HP - 1);
            int gx = clampi(gx0 + sx, 0, HP - 1);
            sF[sy][sx] = imF[gy * HP + gx];
            sM[sy][sx] = imM[gy * HP + gx];
        }
        __syncthreads();

        for (int s = tid; s < (BY + 2) * (BX + 2); s += 512) {
            int sy = s / (BX + 2), sx = s % (BX + 2);
            int uc = clampi(tileY - 1 + sy, 0, HP - 1);
            int vc = clampi(tileX - 1 + sx, 0, HP - 1);
            float pmF = 0.f, pmM = 0.f;
            #pragma unroll
            for (int a = 0; a < 3; a++) {
                int rr = clampi(uc - 2 + a, 0, HP - 1) - gy0;
                #pragma unroll
                for (int bb = 0; bb < 3; bb++) {
                    int cc = clampi(vc - 2 + bb, 0, HP - 1) - gx0;
                    pmF += sF[rr][cc];
                    pmM += sM[rr][cc];
                }
            }
            float dF = sF[uc - gy0][vc - gx0] - pmF * (1.0f / 9.0f);
            float dM = sM[uc - gy0][vc - gx0] - pmM * (1.0f / 9.0f);
            vF[sy][sx] = dF * dF;
            vM[sy][sx] = dM * dM;
        }
        __syncthreads();

        int y = tileY + ty, x = tileX + tx;
        float vsF = 0.f, vsM = 0.f;
        #pragma unroll
        for (int a = -1; a <= 1; a++) {
            int rr = clampi(y + a, 0, HP - 1) - (tileY - 1);
            #pragma unroll
            for (int bb = -1; bb <= 1; bb++) {
                int cc = clampi(x + bb, 0, HP - 1) - (tileX - 1);
                vsF += vF[rr][cc];
                vsM += vM[rr][cc];
            }
        }
        float varF = fmaxf(vsF * (1.0f / 9.0f), 1e-4f);
        float varM = fmaxf(vsM * (1.0f / 9.0f), 1e-4f);
        invF = 1.0f / (varF * 2.0f + 1e-6f);
        invM = 1.0f / (varM * 2.0f + 1e-6f);
        cF = sF[ty + 3][tx + 3];
        cM = sM[ty + 3][tx + 3];
    }

    int y = tileY + ty, x = tileX + tx;
    float eF[8], eM[8];
    float sumF = 0.f, sumM = 0.f;
    if (interior) {
        #pragma unroll
        for (int c = 0; c < 8; c++) {
            float oF = sF[ty + 3 + offdy[c]][tx + 3 + offdx[c]];
            float oM = sM[ty + 3 + offdy[c]][tx + 3 + offdx[c]];
            float dfF = cF - oF, dfM = cM - oM;
            float qF = fminf(dfF * dfF * invF, 50.0f);
            float qM = fminf(dfM * dfM * invM, 50.0f);
            eF[c] = __expf(-qF);
            eM[c] = __expf(-qM);
            sumF += eF[c];
            sumM += eM[c];
        }
    } else {
        #pragma unroll
        for (int c = 0; c < 8; c++) {
            int rr = clampi(y + offdy[c], 0, HP - 1) - gy0;
            int cc = clampi(x + offdx[c], 0, HP - 1) - gx0;
            float oF = sF[rr][cc], oM = sM[rr][cc];
            float dfF = cF - oF, dfM = cM - oM;
            float qF = fminf(dfF * dfF * invF, 50.0f);
            float qM = fminf(dfM * dfM * invM, 50.0f);
            eF[c] = __expf(-qF);
            eM[c] = __expf(-qM);
            sumF += eF[c];
            sumM += eM[c];
        }
    }
    float rF = 1.0f / (sumF + 1e-8f), rM = 1.0f / (sumM + 1e-8f);
    #pragma unroll
    for (int c = 0; c < 8; c++) {
        g_diff[b * 8 + c][y][x] = __float2half(eF[c] * rF - eM[c] * rM);
    }
}

// ------ bilinear upsample (align corners) of diff, |.| partial sums ------
#define UP_ROWS 32
__global__ __launch_bounds__(512) void k_up() {
    const float SCALE = 255.0f / 511.0f;
    __shared__ float xup[18][512];
    __shared__ float red[512];

    int plane = blockIdx.x >> 4;
    int strip = blockIdx.x & 15;
    int yo0 = strip * UP_ROWS;

    int rlo = clampi((int)floorf((float)yo0 * SCALE), 0, HP - 2);
    int rhi = clampi((int)floorf((float)(yo0 + UP_ROWS - 1) * SCALE), 0, HP - 2) + 1;
    int nrows = rhi - rlo + 1;

    int t = threadIdx.x;
    float px = (float)t * SCALE;
    int j0 = clampi((int)floorf(px), 0, HP - 2);
    float fx = px - (float)j0;
    const __half* base = &g_diff[plane][0][0];
    for (int r = 0; r < nrows; r++) {
        const __half* row = base + (rlo + r) * HP;
        xup[r][t] = __half2float(row[j0]) * (1.0f - fx) + __half2float(row[j0 + 1]) * fx;
    }
    __syncthreads();

    float acc = 0.f;
    #pragma unroll
    for (int l = 0; l < UP_ROWS; l++) {
        float pos = (float)(yo0 + l) * SCALE;
        int i0 = clampi((int)floorf(pos), 0, HP - 2);
        float fy = pos - (float)i0;
        float v0 = xup[i0 - rlo][t];
        float v1 = xup[i0 - rlo + 1][t];
        acc += fabsf(v0 * (1.0f - fy) + v1 * fy);
    }
    red[t] = acc;
    __syncthreads();
    #pragma unroll
    for (int s = 256; s > 0; s >>= 1) {
        if (t < s) red[t] += red[t + s];
        __syncthreads();
    }
    if (t == 0) g_part_mind[blockIdx.x] = red[0];
}

// -------- fused epilogue: batch-parallel MI/NMI + partial reductions --------
// 1024 threads = 8 groups of 128 (one per batch), named barriers per group.
__global__ __launch_bounds__(1024) void k_final(float* __restrict__ out) {
    int t = threadIdx.x;
    int g = t >> 7;          // batch
    int lt = t & 127;        // lane within group
    __shared__ float red[1024];
    __shared__ float hp[8][256];
    __shared__ float xh[8][16], yh[8][16];
    __shared__ float s_mi[8][4];
    __shared__ float s_nmi[8];
    __shared__ float s_mind, s_reg;

    // ---- mind partials (1024) ----
    red[t] = g_part_mind[t];
    __syncthreads();
    #pragma unroll
    for (int s = 512; s > 0; s >>= 1) {
        if (t < s) red[t] += red[t + s];
        __syncthreads();
    }
    if (t == 0) s_mind = red[0];
    __syncthreads();

    // ---- reg partials (512) ----
    red[t] = (t < 512) ? g_part_reg[t] : 0.0f;
    __syncthreads();
    #pragma unroll
    for (int s = 512; s > 0; s >>= 1) {
        if (t < s) red[t] += red[t + s];
        __syncthreads();
    }
    if (t == 0) s_reg = red[0];

    // ---- per-batch MI/NMI, batch g handled by group g ----
    // each lane owns 2 consecutive bins; accumulate 32 strip partials (uint2 loads)
    unsigned int c0 = 0, c1 = 0;
    #pragma unroll
    for (int st = 0; st < 32; st++) {
        uint2 u = ((const uint2*)&g_hist_part[g][st][0])[lt];
        c0 += u.x; c1 += u.y;
    }
    float p0 = (float)c0 * (1.0f / 65536.0f);
    float p1 = (float)c1 * (1.0f / 65536.0f);
    hp[g][lt * 2] = p0;
    hp[g][lt * 2 + 1] = p1;
    asm volatile("bar.sync %0, 128;" :: "r"(g + 1) : "memory");

    if (lt < 16) {
        float s = 0.f;
        #pragma unroll
        for (int j = 0; j < 16; j++) s += hp[g][lt * 16 + j];
        xh[g][lt] = s + 1e-5f;
    } else if (lt < 32) {
        int col = lt - 16;
        float s = 0.f;
        #pragma unroll
        for (int i = 0; i < 16; i++) s += hp[g][i * 16 + col];
        yh[g][col] = s + 1e-5f;
    }
    asm volatile("bar.sync %0, 128;" :: "r"(g + 1) : "memory");

    // MI terms for this lane's two bins (bins 2lt, 2lt+1 share the same x-row)
    int i0 = (lt * 2) >> 4;
    float hpe0 = p0 + 1e-5f, hpe1 = p1 + 1e-5f;
    float term = hpe0 * (__logf(hpe0) - __logf(xh[g][i0] * yh[g][(lt * 2) & 15]))
               + hpe1 * (__logf(hpe1) - __logf(xh[g][i0] * yh[g][(lt * 2 + 1) & 15]));
    // warp reduce (fixed order -> deterministic)
    #pragma unroll
    for (int o = 16; o > 0; o >>= 1)
        term += __shfl_down_sync(0xffffffffu, term, o);
    if ((lt & 31) == 0) s_mi[g][lt >> 5] = term;
    asm volatile("bar.sync %0, 128;" :: "r"(g + 1) : "memory");

    if (lt == 0) {
        float mi = s_mi[g][0] + s_mi[g][1] + s_mi[g][2] + s_mi[g][3];
        float hx = 0.f, hy = 0.f;
        #pragma unroll
        for (int k = 0; k < 16; k++) {
            hx -= xh[g][k] * __logf(xh[g][k]);
            hy -= yh[g][k] * __logf(yh[g][k]);
        }
        float se = hx + hy;
        float nmi = (se < 1e-10f) ? 0.0f : 2.0f * mi / se;
        s_nmi[g] = fminf(fmaxf(nmi, -1.0f), 1.0f);
    }
    __syncthreads();

    if (t == 0) {
        float acc = 0.f;
        #pragma unroll
        for (int b = 0; b < BATCH; b++) acc += s_nmi[b];
        float m = fminf(fmaxf(acc * (1.0f / BATCH), -1.0f), 1.0f);
        out[0] = -m
               + 5.0f * (s_mind * (1.0f / 16777216.0f))
               + 0.1f * (s_reg * (1.0f / 524288.0f));
    }
}

// ---------------- launch ----------------
extern "C" void kernel_launch(void* const* d_in, const int* in_sizes, int n_in,
                              void* d_out, int out_size) {
    const float* fixed = (const float*)d_in[0];
    const float* moved = (const float*)d_in[1];
    const float* flow  = (const float*)d_in[2];
    if (n_in >= 3) {
        int fi = -1;
        for (int i = 0; i < 3; i++) if (in_sizes[i] == 2 * BATCH * HF * HF) fi = i;
        if (fi == 0) { flow = (const float*)d_in[0]; fixed = (const float*)d_in[1]; moved = (const float*)d_in[2]; }
        else if (fi == 1) { fixed = (const float*)d_in[0]; flow = (const float*)d_in[1]; moved = (const float*)d_in[2]; }
    }

    k_front<<<1024, 256>>>(fixed, moved, flow);
    k_mind<<<dim3(HP / BX, HP / BY, BATCH), dim3(BX, BY)>>>();
    k_up<<<1024, 512>>>();
    k_final<<<1, 1024>>>((float*)d_out);
}

// round 6
// speedup vs baseline: 1.5987x; 1.0863x over previous
#include <cuda_runtime.h>
#include <cuda_fp16.h>
#include <math.h>

#define BATCH 8
#define HP 256        // pooled H/W
#define HF 512        // full H/W

// Scratch (device globals — no allocation allowed)
__device__ float g_pool[2][BATCH][HP][HP];        // pooled fixed, moved (4MB)
__device__ __half g_diff[BATCH * 8][HP][HP];      // mind descriptor diff (8MB, fp16)
__device__ unsigned int g_hist_part[BATCH][32][256];
__device__ unsigned int g_hist_agg[BATCH][256];
__device__ float g_part_mind[1024];
__device__ float g_part_reg[512];

__device__ __forceinline__ float san(float v) { return (v == v) ? v : 0.0f; }
__device__ __forceinline__ int clampi(int v, int lo, int hi) { return min(max(v, lo), hi); }

// ============ fused front-end: pool fixed (+hist), pool moved, flow regularizer ====
__global__ __launch_bounds__(256) void k_front(const float* __restrict__ fixed,
                                               const float* __restrict__ moved,
                                               const float* __restrict__ flow) {
    int blk = blockIdx.x;
    int t = threadIdx.x;

    if (blk < 512) {
        int p = blk >> 8;            // 0 fixed, 1 moved
        int b = (blk >> 5) & 7;
        int st = blk & 31;           // 8 pooled rows per strip
        int tt = t & 127;            // float4 col group -> pooled cols 2tt, 2tt+1
        int half = t >> 7;
        const float* src = (p == 0 ? fixed : moved) + (size_t)b * HF * HF;
        const float* msrc = moved + (size_t)b * HF * HF;

        __shared__ unsigned int sh[256];
        if (p == 0) {
            sh[t] = 0u;
            __syncthreads();
        }

        #pragma unroll
        for (int j = 0; j < 4; j++) {
            int y = st * 8 + half * 4 + j;
            const float4* r0 = (const float4*)(src + (size_t)(2 * y) * HF) + tt;
            float4 a = r0[0];
            float4 c = r0[HF / 4];
            float p0 = 0.25f * (san(a.x) + san(a.y) + san(c.x) + san(c.y));
            float p1 = 0.25f * (san(a.z) + san(a.w) + san(c.z) + san(c.w));
            ((float2*)&g_pool[p][b][y][0])[tt] = make_float2(p0, p1);
            if (p == 0) {
                float4 m = ((const float4*)(msrc + (size_t)(2 * y) * HF))[tt];
                // sample (2y, 4tt) and (2y, 4tt+2); searchsorted-left == ceil(v*16)-1
                float xf0 = fminf(fmaxf((san(a.x) + 1.0f) * 0.5f, 0.001f), 0.999f);
                float yf0 = fminf(fmaxf((san(m.x) + 1.0f) * 0.5f, 0.001f), 0.999f);
                int xb0 = clampi((int)ceilf(xf0 * 16.0f) - 1, 0, 15);
                int yb0 = clampi((int)ceilf(yf0 * 16.0f) - 1, 0, 15);
                atomicAdd(&sh[xb0 * 16 + yb0], 1u);
                float xf1 = fminf(fmaxf((san(a.z) + 1.0f) * 0.5f, 0.001f), 0.999f);
                float yf1 = fminf(fmaxf((san(m.z) + 1.0f) * 0.5f, 0.001f), 0.999f);
                int xb1 = clampi((int)ceilf(xf1 * 16.0f) - 1, 0, 15);
                int yb1 = clampi((int)ceilf(yf1 * 16.0f) - 1, 0, 15);
                atomicAdd(&sh[xb1 * 16 + yb1], 1u);
            }
        }
        if (p == 0) {
            __syncthreads();
            g_hist_part[b][st][t] = sh[t];
        }
    } else {
        // ---- regularizer: fused pool of flow + sobel/laplacian, 4 rows per block ----
        int q = blk - 512;
        int b = q >> 6;
        int st = q & 63;
        int tt = t & 127;
        int sel = t >> 7;    // 0 -> u, 1 -> v
        const float* base = flow + ((size_t)b * 2 + sel) * HF * HF;

        __shared__ float su[6][256];
        __shared__ float sv[6][256];
        float (*sbuf)[256] = sel ? sv : su;

        #pragma unroll
        for (int r = 0; r < 6; r++) {
            int py = clampi(st * 4 - 1 + r, 0, HP - 1);
            const float4* q0 = (const float4*)(base + (size_t)(2 * py) * HF) + tt;
            float4 a = q0[0];
            float4 c = q0[HF / 4];
            sbuf[r][2 * tt]     = 0.25f * (san(a.x) + san(a.y) + san(c.x) + san(c.y));
            sbuf[r][2 * tt + 1] = 0.25f * (san(a.z) + san(a.w) + san(c.z) + san(c.w));
        }
        __syncthreads();

        int xm = max(t - 1, 0), xp = min(t + 1, HP - 1);
        float acc = 0.f;
        #pragma unroll
        for (int j = 0; j < 4; j++) {
            int r = j + 1;
            float u00 = su[r - 1][xm], u01 = su[r - 1][t], u02 = su[r - 1][xp];
            float u10 = su[r][xm],     u11 = su[r][t],     u12 = su[r][xp];
            float u20 = su[r + 1][xm], u21 = su[r + 1][t], u22 = su[r + 1][xp];
            float v00 = sv[r - 1][xm], v01 = sv[r - 1][t], v02 = sv[r - 1][xp];
            float v10 = sv[r][xm],     v11 = sv[r][t],     v12 = sv[r][xp];
            float v20 = sv[r + 1][xm], v21 = sv[r + 1][t], v22 = sv[r + 1][xp];

            float gxu = (u02 + 2.f * u12 + u22) - (u00 + 2.f * u10 + u20);
            float gyu = (u20 + 2.f * u21 + u22) - (u00 + 2.f * u01 + u02);
            float lpu = u01 + u10 + u12 + u21 - 4.f * u11;
            float gxv = (v02 + 2.f * v12 + v22) - (v00 + 2.f * v10 + v20);
            float gyv = (v20 + 2.f * v21 + v22) - (v00 + 2.f * v01 + v02);
            float lpv = v01 + v10 + v12 + v21 - 4.f * v11;

            float gm = gxu * gxu + gyu * gyu + gxv * gxv + gyv * gyv;
            float lm = lpu * lpu + lpv * lpv;
            acc += fminf(gm, 100.0f) + fminf(lm, 100.0f);
        }

        __shared__ float red[256];
        red[t] = acc;
        __syncthreads();
        #pragma unroll
        for (int s = 128; s > 0; s >>= 1) {
            if (t < s) red[t] += red[t + s];
            __syncthreads();
        }
        if (t == 0) g_part_reg[q] = red[0];
    }
}

// ---------------- MIND descriptors for both images, write diff (fp16) ----------------
#define BX 32
#define BY 16
#define SW 38   // BX + 6
__global__ __launch_bounds__(512) void k_mind() {
    __shared__ float sF[BY + 6][SW];
    __shared__ float sM[BY + 6][SW];
    __shared__ float hF[BY + 4][BX + 2];
    __shared__ float hM[BY + 4][BX + 2];
    __shared__ float vF[BY + 2][BX + 2];
    __shared__ float vM[BY + 2][BX + 2];
    __shared__ float hvF[BY + 2][BX];
    __shared__ float hvM[BY + 2][BX];

    int b = blockIdx.z;
    int tileX = blockIdx.x * BX, tileY = blockIdx.y * BY;
    int gx0 = tileX - 3, gy0 = tileY - 3;
    int tid = threadIdx.y * BX + threadIdx.x;
    int ty = threadIdx.y, tx = threadIdx.x;
    const float* imF = &g_pool[0][b][0][0];
    const float* imM = &g_pool[1][b][0][0];

    bool interior = (blockIdx.x >= 1) && (blockIdx.x <= 6) &&
                    (blockIdx.y >= 1) && (blockIdx.y <= 14);

    const int offdx[8] = {-2, -2, -2, 0, 0, 2, 2, 2};
    const int offdy[8] = {-2, 0, 2, -2, 2, -2, 0, 2};

    float cF, cM, invF, invM;

    if (interior) {
        for (int s = tid; s < (BY + 6) * SW; s += 512) {
            int sy = s / SW, sx = s % SW;
            sF[sy][sx] = imF[(gy0 + sy) * HP + gx0 + sx];
            sM[sy][sx] = imM[(gy0 + sy) * HP + gx0 + sx];
        }
        __syncthreads();

        for (int s = tid; s < (BY + 4) * (BX + 2); s += 512) {
            int sy = s / (BX + 2), sx = s % (BX + 2);
            hF[sy][sx] = sF[sy][sx] + sF[sy][sx + 1] + sF[sy][sx + 2];
            hM[sy][sx] = sM[sy][sx] + sM[sy][sx + 1] + sM[sy][sx + 2];
        }
        __syncthreads();

        for (int s = tid; s < (BY + 2) * (BX + 2); s += 512) {
            int sy = s / (BX + 2), sx = s % (BX + 2);
            float pmF = hF[sy][sx] + hF[sy + 1][sx] + hF[sy + 2][sx];
            float pmM = hM[sy][sx] + hM[sy + 1][sx] + hM[sy + 2][sx];
            float dF = sF[sy + 2][sx + 2] - pmF * (1.0f / 9.0f);
            float dM = sM[sy + 2][sx + 2] - pmM * (1.0f / 9.0f);
            vF[sy][sx] = dF * dF;
            vM[sy][sx] = dM * dM;
        }
        __syncthreads();

        for (int s = tid; s < (BY + 2) * BX; s += 512) {
            int sy = s >> 5, sx = s & 31;
            hvF[sy][sx] = vF[sy][sx] + vF[sy][sx + 1] + vF[sy][sx + 2];
            hvM[sy][sx] = vM[sy][sx] + vM[sy][sx + 1] + vM[sy][sx + 2];
        }
        __syncthreads();

        float varF = fmaxf((hvF[ty][tx] + hvF[ty + 1][tx] + hvF[ty + 2][tx]) * (1.0f / 9.0f), 1e-4f);
        float varM = fmaxf((hvM[ty][tx] + hvM[ty + 1][tx] + hvM[ty + 2][tx]) * (1.0f / 9.0f), 1e-4f);
        invF = 1.0f / (varF * 2.0f + 1e-6f);
        invM = 1.0f / (varM * 2.0f + 1e-6f);
        cF = sF[ty + 3][tx + 3];
        cM = sM[ty + 3][tx + 3];
    } else {
        for (int s = tid; s < (BY + 6) * SW; s += 512) {
            int sy = s / SW, sx = s % SW;
            int gy = clampi(gy0 + sy, 0, HP - 1);
            int gx = clampi(gx0 + sx, 0, HP - 1);
            sF[sy][sx] = imF[gy * HP + gx];
            sM[sy][sx] = imM[gy * HP + gx];
        }
        __syncthreads();

        for (int s = tid; s < (BY + 2) * (BX + 2); s += 512) {
            int sy = s / (BX + 2), sx = s % (BX + 2);
            int uc = clampi(tileY - 1 + sy, 0, HP - 1);
            int vc = clampi(tileX - 1 + sx, 0, HP - 1);
            float pmF = 0.f, pmM = 0.f;
            #pragma unroll
            for (int a = 0; a < 3; a++) {
                int rr = clampi(uc - 2 + a, 0, HP - 1) - gy0;
                #pragma unroll
                for (int bb = 0; bb < 3; bb++) {
                    int cc = clampi(vc - 2 + bb, 0, HP - 1) - gx0;
                    pmF += sF[rr][cc];
                    pmM += sM[rr][cc];
                }
            }
            float dF = sF[uc - gy0][vc - gx0] - pmF * (1.0f / 9.0f);
            float dM = sM[uc - gy0][vc - gx0] - pmM * (1.0f / 9.0f);
            vF[sy][sx] = dF * dF;
            vM[sy][sx] = dM * dM;
        }
        __syncthreads();

        int y = tileY + ty, x = tileX + tx;
        float vsF = 0.f, vsM = 0.f;
        #pragma unroll
        for (int a = -1; a <= 1; a++) {
            int rr = clampi(y + a, 0, HP - 1) - (tileY - 1);
            #pragma unroll
            for (int bb = -1; bb <= 1; bb++) {
                int cc = clampi(x + bb, 0, HP - 1) - (tileX - 1);
                vsF += vF[rr][cc];
                vsM += vM[rr][cc];
            }
        }
        float varF = fmaxf(vsF * (1.0f / 9.0f), 1e-4f);
        float varM = fmaxf(vsM * (1.0f / 9.0f), 1e-4f);
        invF = 1.0f / (varF * 2.0f + 1e-6f);
        invM = 1.0f / (varM * 2.0f + 1e-6f);
        cF = sF[ty + 3][tx + 3];
        cM = sM[ty + 3][tx + 3];
    }

    int y = tileY + ty, x = tileX + tx;
    float eF[8], eM[8];
    float sumF = 0.f, sumM = 0.f;
    if (interior) {
        #pragma unroll
        for (int c = 0; c < 8; c++) {
            float oF = sF[ty + 3 + offdy[c]][tx + 3 + offdx[c]];
            float oM = sM[ty + 3 + offdy[c]][tx + 3 + offdx[c]];
            float dfF = cF - oF, dfM = cM - oM;
            float qF = fminf(dfF * dfF * invF, 50.0f);
            float qM = fminf(dfM * dfM * invM, 50.0f);
            eF[c] = __expf(-qF);
            eM[c] = __expf(-qM);
            sumF += eF[c];
            sumM += eM[c];
        }
    } else {
        #pragma unroll
        for (int c = 0; c < 8; c++) {
            int rr = clampi(y + offdy[c], 0, HP - 1) - gy0;
            int cc = clampi(x + offdx[c], 0, HP - 1) - gx0;
            float oF = sF[rr][cc], oM = sM[rr][cc];
            float dfF = cF - oF, dfM = cM - oM;
            float qF = fminf(dfF * dfF * invF, 50.0f);
            float qM = fminf(dfM * dfM * invM, 50.0f);
            eF[c] = __expf(-qF);
            eM[c] = __expf(-qM);
            sumF += eF[c];
            sumM += eM[c];
        }
    }
    float rF = 1.0f / (sumF + 1e-8f), rM = 1.0f / (sumM + 1e-8f);
    #pragma unroll
    for (int c = 0; c < 8; c++) {
        g_diff[b * 8 + c][y][x] = __float2half(eF[c] * rF - eM[c] * rM);
    }
}

// ------ bilinear upsample (align corners) of diff, |.| partial sums ------
// Blocks 0..7 additionally collapse hist strip-partials (overwrite semantics).
#define UP_ROWS 32
__global__ __launch_bounds__(512) void k_up() {
    const float SCALE = 255.0f / 511.0f;
    __shared__ float xup[18][512];
    __shared__ float red[512];

    int t = threadIdx.x;

    if (blockIdx.x < 8 && t < 256) {
        unsigned int c = 0;
        #pragma unroll
        for (int st = 0; st < 32; st++) c += g_hist_part[blockIdx.x][st][t];
        g_hist_agg[blockIdx.x][t] = c;
    }

    int plane = blockIdx.x >> 4;
    int strip = blockIdx.x & 15;
    int yo0 = strip * UP_ROWS;

    int rlo = clampi((int)floorf((float)yo0 * SCALE), 0, HP - 2);
    int rhi = clampi((int)floorf((float)(yo0 + UP_ROWS - 1) * SCALE), 0, HP - 2) + 1;
    int nrows = rhi - rlo + 1;

    float px = (float)t * SCALE;
    int j0 = clampi((int)floorf(px), 0, HP - 2);
    float fx = px - (float)j0;
    const __half* base = &g_diff[plane][0][0];
    for (int r = 0; r < nrows; r++) {
        const __half* row = base + (rlo + r) * HP;
        xup[r][t] = __half2float(row[j0]) * (1.0f - fx) + __half2float(row[j0 + 1]) * fx;
    }
    __syncthreads();

    float acc = 0.f;
    #pragma unroll
    for (int l = 0; l < UP_ROWS; l++) {
        float pos = (float)(yo0 + l) * SCALE;
        int i0 = clampi((int)floorf(pos), 0, HP - 2);
        float fy = pos - (float)i0;
        float v0 = xup[i0 - rlo][t];
        float v1 = xup[i0 - rlo + 1][t];
        acc += fabsf(v0 * (1.0f - fy) + v1 * fy);
    }
    red[t] = acc;
    __syncthreads();
    #pragma unroll
    for (int s = 256; s > 0; s >>= 1) {
        if (t < s) red[t] += red[t + s];
        __syncthreads();
    }
    if (t == 0) g_part_mind[blockIdx.x] = red[0];
}

// -------- warp-specialized epilogue: hist-MI (warps 0-7), mind (8-15), reg (16-19) ----
__global__ __launch_bounds__(1024) void k_final(float* __restrict__ out) {
    int t = threadIdx.x;
    int w = t >> 5;
    int lane = t & 31;
    __shared__ float hp[8][256];
    __shared__ float xh[8][16], yh[8][16];
    __shared__ float s_nmi[8];
    __shared__ float s_mind_p[8], s_reg_p[4];

    if (w < 8) {
        // ---- batch w: MI/NMI entirely within this warp ----
        int b = w;
        // lane owns 8 consecutive bins
        uint4 u0 = ((const uint4*)&g_hist_agg[b][0])[lane * 2];
        uint4 u1 = ((const uint4*)&g_hist_agg[b][0])[lane * 2 + 1];
        float p[8];
        p[0] = (float)u0.x * (1.0f / 65536.0f); p[1] = (float)u0.y * (1.0f / 65536.0f);
        p[2] = (float)u0.z * (1.0f / 65536.0f); p[3] = (float)u0.w * (1.0f / 65536.0f);
        p[4] = (float)u1.x * (1.0f / 65536.0f); p[5] = (float)u1.y * (1.0f / 65536.0f);
        p[6] = (float)u1.z * (1.0f / 65536.0f); p[7] = (float)u1.w * (1.0f / 65536.0f);
        #pragma unroll
        for (int k = 0; k < 8; k++) hp[b][lane * 8 + k] = p[k];
        __syncwarp();
        if (lane < 16) {
            float s = 0.f;
            #pragma unroll
            for (int j = 0; j < 16; j++) s += hp[b][lane * 16 + j];
            xh[b][lane] = s + 1e-5f;
        } else {
            int col = lane - 16;
            float s = 0.f;
            #pragma unroll
            for (int i = 0; i < 16; i++) s += hp[b][i * 16 + col];
            yh[b][col] = s + 1e-5f;
        }
        __syncwarp();
        int row = (lane * 8) >> 4;        // bins 8*lane..8*lane+7 share one x-row
        float xr = xh[b][row];
        int cbase = (lane * 8) & 15;      // 0 or 8
        float term = 0.f;
        #pragma unroll
        for (int k = 0; k < 8; k++) {
            float hpe = p[k] + 1e-5f;
            term += hpe * (__logf(hpe) - __logf(xr * yh[b][cbase + k]));
        }
        #pragma unroll
        for (int o = 16; o > 0; o >>= 1)
            term += __shfl_down_sync(0xffffffffu, term, o);
        if (lane == 0) {
            float mi = term;
            float hx = 0.f, hy = 0.f;
            #pragma unroll
            for (int k = 0; k < 16; k++) {
                hx -= xh[b][k] * __logf(xh[b][k]);
                hy -= yh[b][k] * __logf(yh[b][k]);
            }
            float se = hx + hy;
            float nmi = (se < 1e-10f) ? 0.0f : 2.0f * mi / se;
            s_nmi[b] = fminf(fmaxf(nmi, -1.0f), 1.0f);
        }
    } else if (w < 16) {
        // ---- mind partials: 1024 floats, 8 warps, float4 each ----
        int i = t - 256;   // 0..255
        float4 v = ((const float4*)g_part_mind)[i];
        float s = (v.x + v.y) + (v.z + v.w);
        #pragma unroll
        for (int o = 16; o > 0; o >>= 1)
            s += __shfl_down_sync(0xffffffffu, s, o);
        if (lane == 0) s_mind_p[w - 8] = s;
    } else if (w < 20) {
        // ---- reg partials: 512 floats, 4 warps, float4 each ----
        int i = t - 512;   // 0..127
        float4 v = ((const float4*)g_part_reg)[i];
        float s = (v.x + v.y) + (v.z + v.w);
        #pragma unroll
        for (int o = 16; o > 0; o >>= 1)
            s += __shfl_down_sync(0xffffffffu, s, o);
        if (lane == 0) s_reg_p[w - 16] = s;
    }
    __syncthreads();

    if (t == 0) {
        float mind = 0.f;
        #pragma unroll
        for (int k = 0; k < 8; k++) mind += s_mind_p[k];
        float reg = (s_reg_p[0] + s_reg_p[1]) + (s_reg_p[2] + s_reg_p[3]);
        float acc = 0.f;
        #pragma unroll
        for (int b = 0; b < BATCH; b++) acc += s_nmi[b];
        float m = fminf(fmaxf(acc * (1.0f / BATCH), -1.0f), 1.0f);
        out[0] = -m
               + 5.0f * (mind * (1.0f / 16777216.0f))
               + 0.1f * (reg * (1.0f / 524288.0f));
    }
}

// ---------------- launch ----------------
extern "C" void kernel_launch(void* const* d_in, const int* in_sizes, int n_in,
                              void* d_out, int out_size) {
    const float* fixed = (const float*)d_in[0];
    const float* moved = (const float*)d_in[1];
    const float* flow  = (const float*)d_in[2];
    if (n_in >= 3) {
        int fi = -1;
        for (int i = 0; i < 3; i++) if (in_sizes[i] == 2 * BATCH * HF * HF) fi = i;
        if (fi == 0) { flow = (const float*)d_in[0]; fixed = (const float*)d_in[1]; moved = (const float*)d_in[2]; }
        else if (fi == 1) { fixed = (const float*)d_in[0]; flow = (const float*)d_in[1]; moved = (const float*)d_in[2]; }
    }

    k_front<<<1024, 256>>>(fixed, moved, flow);
    k_mind<<<dim3(HP / BX, HP / BY, BATCH), dim3(BX, BY)>>>();
    k_up<<<1024, 512>>>();
    k_final<<<1, 1024>>>((float*)d_out);
}